// round 1
// baseline (speedup 1.0000x reference)
#include <cuda_runtime.h>
#include <math.h>

#define N   16384
#define D   128
#define BM  64
#define BN  64
#define NT  256

// Scratch (allocation-free rule: __device__ globals)
__device__ float g_Q[N * D];
__device__ float g_K[N * D];
__device__ float g_V[N * D];
__device__ int   g_uid[N];

// ---------------------------------------------------------------------------
// user_ids dtype normalization: reference declares int64 but JAX without x64
// canonicalizes to int32. Detect on-device: if int64, the odd 32-bit words of
// the first 16 elements are all zero (ids < 512). For int32 data those words
// are 16 independent uniform values in [0,512) — all-zero prob ~512^-16.
// Only the first 128 bytes are read for detection (safe for either width).
// ---------------------------------------------------------------------------
__global__ void prep_uid_kernel(const void* __restrict__ uptr) {
    const int* w32 = (const int*)uptr;
    bool is64 = true;
#pragma unroll
    for (int k = 0; k < 16; ++k)
        if (w32[2 * k + 1] != 0) is64 = false;
    int i = blockIdx.x * blockDim.x + threadIdx.x;
    int v;
    if (is64) v = (int)((const long long*)uptr)[i];
    else      v = w32[i];
    g_uid[i] = v;
}

// ---------------------------------------------------------------------------
// QKV projection: out = x @ W^T  for W in {Wq, Wk, Wv}  (blockIdx.y selects)
// CTA computes a [64 x 128] output block. 256 threads as 16x16; each thread
// owns 4 rows x 8 cols (cols strided by 16 for conflict-free smem reads).
// ---------------------------------------------------------------------------
__global__ void __launch_bounds__(NT, 2)
qkv_kernel(const float* __restrict__ x,
           const float* __restrict__ Wq,
           const float* __restrict__ Wk,
           const float* __restrict__ Wv) {
    extern __shared__ float sm[];
    float* xs = sm;              // [64][128]
    float* ws = sm + BM * D;     // [128][129]  (pitch 129: conflict-free reads)

    const int tid = threadIdx.x;
    const int tx = tid & 15;
    const int ty = tid >> 4;

    const float* W = (blockIdx.y == 0) ? Wq : ((blockIdx.y == 1) ? Wk : Wv);
    float* outp    = (blockIdx.y == 0) ? g_Q : ((blockIdx.y == 1) ? g_K : g_V);

    const int rb = blockIdx.x * BM;

    for (int e = tid; e < BM * D; e += NT) xs[e] = x[rb * D + e];
    for (int e = tid; e < D * D; e += NT) {
        int n = e >> 7, d = e & 127;
        ws[n * 129 + d] = W[e];
    }
    __syncthreads();

    float acc[4][8];
#pragma unroll
    for (int i = 0; i < 4; ++i)
#pragma unroll
        for (int c = 0; c < 8; ++c) acc[i][c] = 0.0f;

#pragma unroll 4
    for (int d = 0; d < D; ++d) {
        float a[4], w[8];
#pragma unroll
        for (int i = 0; i < 4; ++i) a[i] = xs[(ty * 4 + i) * D + d];
#pragma unroll
        for (int c = 0; c < 8; ++c) w[c] = ws[(tx + 16 * c) * 129 + d];
#pragma unroll
        for (int i = 0; i < 4; ++i)
#pragma unroll
            for (int c = 0; c < 8; ++c) acc[i][c] += a[i] * w[c];
    }

#pragma unroll
    for (int i = 0; i < 4; ++i)
#pragma unroll
        for (int c = 0; c < 8; ++c)
            outp[(rb + ty * 4 + i) * D + tx + 16 * c] = acc[i][c];
}

// ---------------------------------------------------------------------------
// Fused attention, flash style. CTA owns BM=64 query rows; streams KV in
// BN=64 blocks (K/V live in L2: 16 MB total). Threads 16x16; thread computes
// a 4x4 S-tile in registers, online softmax state per row is replicated
// across the 16-lane row group (half-warp shfl reductions), P stays in
// registers and is broadcast to the row group via shfl for the PV GEMM.
// Everything is done in log2 domain: t = s * (log2e/sqrt(D)) + bias*log2e.
// ---------------------------------------------------------------------------
__global__ void __launch_bounds__(NT, 2)
attn_kernel(float* __restrict__ out) {
    extern __shared__ float sm[];
    float* Qs = sm;                          // [64][128]
    float* Ks = Qs + BM * D;                 // [64][129]
    float* Vs = Ks + BN * 129;               // [64][128]
    int*   uks = (int*)(Vs + BN * D);        // [64]

    const int tid = threadIdx.x;
    const int tx = tid & 15;
    const int ty = tid >> 4;
    const int lane = tid & 31;
    const int qb = blockIdx.x * BM;

    // Q block -> smem (stays resident for all KV iterations)
    for (int e = tid; e < BM * D; e += NT) Qs[e] = g_Q[qb * D + e];

    int uq[4];
#pragma unroll
    for (int i = 0; i < 4; ++i) uq[i] = g_uid[qb + ty * 4 + i];

    float m[4], l[4], acc[4][8];
#pragma unroll
    for (int i = 0; i < 4; ++i) {
        m[i] = -INFINITY;
        l[i] = 0.0f;
#pragma unroll
        for (int c = 0; c < 8; ++c) acc[i][c] = 0.0f;
    }

    const float C1 = 1.4426950408889634f / 11.313708498984760f; // log2e / sqrt(128)
    const float C2 = 5.0f * 1.4426950408889634f;                 // bias * log2e

    const int srcbase = lane & 16;

    for (int kb = 0; kb < N / BN; ++kb) {
        __syncthreads();  // previous iteration's smem reads complete
        const int kbase = kb * BN;
        for (int e = tid; e < BN * D; e += NT) {
            int n = e >> 7, d = e & 127;
            float kv = g_K[(kbase + n) * D + d];
            float vv = g_V[(kbase + n) * D + d];
            Ks[n * 129 + d] = kv;
            Vs[e] = vv;
        }
        if (tid < BN) uks[tid] = g_uid[kbase + tid];
        __syncthreads();

        // S = Q @ K^T  (4x4 per thread)
        float s[4][4];
#pragma unroll
        for (int i = 0; i < 4; ++i)
#pragma unroll
            for (int j = 0; j < 4; ++j) s[i][j] = 0.0f;

#pragma unroll 4
        for (int d = 0; d < D; ++d) {
            float a[4], b[4];
#pragma unroll
            for (int i = 0; i < 4; ++i) a[i] = Qs[(ty * 4 + i) * D + d];
#pragma unroll
            for (int j = 0; j < 4; ++j) b[j] = Ks[(tx * 4 + j) * 129 + d];
#pragma unroll
            for (int i = 0; i < 4; ++i)
#pragma unroll
                for (int j = 0; j < 4; ++j) s[i][j] += a[i] * b[j];
        }

        int uk4[4];
#pragma unroll
        for (int j = 0; j < 4; ++j) uk4[j] = uks[tx * 4 + j];

        // log2 domain + same-user bias
#pragma unroll
        for (int i = 0; i < 4; ++i)
#pragma unroll
            for (int j = 0; j < 4; ++j)
                s[i][j] = s[i][j] * C1 + ((uq[i] == uk4[j]) ? C2 : 0.0f);

        // Online softmax per row (row group = 16 lanes of a half-warp)
        float p[4][4];
#pragma unroll
        for (int i = 0; i < 4; ++i) {
            float mx = fmaxf(fmaxf(s[i][0], s[i][1]), fmaxf(s[i][2], s[i][3]));
#pragma unroll
            for (int o = 8; o >= 1; o >>= 1)
                mx = fmaxf(mx, __shfl_xor_sync(0xffffffffu, mx, o));
            float mn = fmaxf(m[i], mx);
            float alpha = exp2f(m[i] - mn);
            m[i] = mn;
            float rs = 0.0f;
#pragma unroll
            for (int j = 0; j < 4; ++j) {
                p[i][j] = exp2f(s[i][j] - mn);
                rs += p[i][j];
            }
#pragma unroll
            for (int o = 8; o >= 1; o >>= 1)
                rs += __shfl_xor_sync(0xffffffffu, rs, o);
            l[i] = l[i] * alpha + rs;
#pragma unroll
            for (int c = 0; c < 8; ++c) acc[i][c] *= alpha;
        }

        // PV: O += P @ V.  P broadcast from owner lane via shfl (no smem).
        for (int jb = 0; jb < 16; ++jb) {
#pragma unroll
            for (int jj = 0; jj < 4; ++jj) {
                const int j = jb * 4 + jj;
                const int src = srcbase | jb;
                float p0 = __shfl_sync(0xffffffffu, p[0][jj], src);
                float p1 = __shfl_sync(0xffffffffu, p[1][jj], src);
                float p2 = __shfl_sync(0xffffffffu, p[2][jj], src);
                float p3 = __shfl_sync(0xffffffffu, p[3][jj], src);
#pragma unroll
                for (int c = 0; c < 8; ++c) {
                    float v = Vs[j * D + tx + 16 * c];
                    acc[0][c] += p0 * v;
                    acc[1][c] += p1 * v;
                    acc[2][c] += p2 * v;
                    acc[3][c] += p3 * v;
                }
            }
        }
    }

    // Normalize and write
#pragma unroll
    for (int i = 0; i < 4; ++i) {
        float inv = 1.0f / l[i];
#pragma unroll
        for (int c = 0; c < 8; ++c)
            out[(qb + ty * 4 + i) * D + tx + 16 * c] = acc[i][c] * inv;
    }
}

// ---------------------------------------------------------------------------
extern "C" void kernel_launch(void* const* d_in, const int* in_sizes, int n_in,
                              void* d_out, int out_size) {
    const float* x  = (const float*)d_in[0];
    const void*  u  = d_in[1];
    const float* Wq = (const float*)d_in[2];
    const float* Wk = (const float*)d_in[3];
    const float* Wv = (const float*)d_in[4];
    float* out = (float*)d_out;

    const int qkv_smem  = (BM * D + D * 129) * (int)sizeof(float);
    const int attn_smem = (BM * D + BN * 129 + BN * D) * (int)sizeof(float)
                          + BN * (int)sizeof(int);
    cudaFuncSetAttribute(qkv_kernel,  cudaFuncAttributeMaxDynamicSharedMemorySize, qkv_smem);
    cudaFuncSetAttribute(attn_kernel, cudaFuncAttributeMaxDynamicSharedMemorySize, attn_smem);

    prep_uid_kernel<<<N / 256, 256>>>(u);
    qkv_kernel<<<dim3(N / BM, 3), NT, qkv_smem>>>(x, Wq, Wk, Wv);
    attn_kernel<<<N / BM, NT, attn_smem>>>(out);
}